// round 15
// baseline (speedup 1.0000x reference)
#include <cuda_runtime.h>
#include <cuda_fp16.h>
#include <cuda_bf16.h>
#include <cstdint>

// Problem constants
#define TT 256
#define BB 1024
#define OBS 128
#define LS 128
#define HH 128
#define NA 18
#define MROWS (TT*BB)          // 262144

// ---------------------------------------------------------------------------
// Scratch (device globals; no cudaMalloc allowed)
// ---------------------------------------------------------------------------
__device__ float g_h1[(size_t)MROWS * 128];   // encoder layer-1 out
__device__ float g_h2[(size_t)MROWS * 32];    // encoder layer-2 out
__device__ float g_h3[(size_t)MROWS * 128];   // encoder layer-3 out
__device__ float g_Z [(size_t)MROWS * 512];   // precomputed input gates + biases

// ---------------------------------------------------------------------------
// f32x2 packed-FMA helpers (exact fp32 math; 2 MACs per issued inst)
// ---------------------------------------------------------------------------
__device__ __forceinline__ void ffma2(uint64_t& acc, uint64_t a, uint64_t b) {
    asm("fma.rn.f32x2 %0, %1, %2, %0;" : "+l"(acc) : "l"(a), "l"(b));
}
__device__ __forceinline__ uint64_t pack2(float x, float y) {
    uint64_t r;
    asm("mov.b64 %0, {%1, %2};" : "=l"(r) : "f"(x), "f"(y));
    return r;
}
__device__ __forceinline__ void unpack2(uint64_t v, float& lo, float& hi) {
    asm("mov.b64 {%0, %1}, %2;" : "=f"(lo), "=f"(hi) : "l"(v));
}

// ---------------------------------------------------------------------------
// Fast nonlinearities (MUFU; fma pipe stays free)
// ---------------------------------------------------------------------------
__device__ __forceinline__ float sigm_fast(float x) {
    x = fminf(fmaxf(x, -30.f), 30.f);
    return __fdividef(1.f, 1.f + __expf(-x));
}
__device__ __forceinline__ float tanh_fast(float x) {
    x = fminf(fmaxf(x, -15.f), 15.f);
    float e = __expf(-2.f * x);
    return __fdividef(1.f - e, 1.f + e);
}

// ---------------------------------------------------------------------------
// NEW: 2-CTA/SM GEMM. Tile 128x128, 512 threads, K staged in 64-chunks so
// smem = 66.5KB/CTA -> 2 CTAs/SM (8 warps/SMSP) hides LDS/issue latency.
// Per-thread 8 rows x 4 cols; A-frags warp-uniform broadcasts; B-frags
// lane-contiguous LDS.128.
//   C[M][128-tile] = act( A[M][K] @ W[N][K]^T + b1 (+b2) )
// ---------------------------------------------------------------------------
template<int KT, bool RELU>
__global__ void __launch_bounds__(512, 2) gemm_b2(
    const float* __restrict__ A, const float* __restrict__ W,
    const float* __restrict__ bias1, const float* __restrict__ bias2,
    float* __restrict__ C, int N)
{
    constexpr int BPP = 132;        // padded B leading dim
    extern __shared__ float smg[];
    float* As = smg;                // 64 * 128
    float* Bs = smg + 64 * 128;     // 64 * 132

    const int  tid  = threadIdx.x;
    const int  lane = tid & 31;
    const int  wid  = tid >> 5;          // 0..15
    const int  rbase = wid * 8;
    const int  cg    = lane * 4;
    const long row0 = (long)blockIdx.x * 128;
    const int  c0   = blockIdx.y * 128;

    uint64_t acc2[4][4];
    #pragma unroll
    for (int rp = 0; rp < 4; ++rp)
        #pragma unroll
        for (int c = 0; c < 4; ++c) acc2[rp][c] = 0ull;

    for (int kc = 0; kc < KT; kc += 64) {
        // Stage A chunk transposed: As[k][row], 128 rows x 64 k
        for (int idx = tid; idx < 16 * 128; idx += 512) {
            int kq = idx >> 7, r = idx & 127;
            float4 v = *reinterpret_cast<const float4*>(
                A + (row0 + r) * KT + kc + kq * 4);
            As[(kq*4+0)*128 + r] = v.x;
            As[(kq*4+1)*128 + r] = v.y;
            As[(kq*4+2)*128 + r] = v.z;
            As[(kq*4+3)*128 + r] = v.w;
        }
        // Stage B chunk transposed: Bs[k][col], 128 cols x 64 k
        for (int idx = tid; idx < 16 * 128; idx += 512) {
            int kq = idx >> 7, jj = idx & 127;
            float4 v = *reinterpret_cast<const float4*>(
                W + (long)(c0 + jj) * KT + kc + kq * 4);
            Bs[(kq*4+0)*BPP + jj] = v.x;
            Bs[(kq*4+1)*BPP + jj] = v.y;
            Bs[(kq*4+2)*BPP + jj] = v.z;
            Bs[(kq*4+3)*BPP + jj] = v.w;
        }
        __syncthreads();

        #pragma unroll 4
        for (int k = 0; k < 64; ++k) {
            ulonglong2 av0 = *reinterpret_cast<const ulonglong2*>(&As[k * 128 + rbase]);
            ulonglong2 av1 = *reinterpret_cast<const ulonglong2*>(&As[k * 128 + rbase + 4]);
            float4 bv = *reinterpret_cast<const float4*>(&Bs[k * BPP + cg]);
            uint64_t bd0 = pack2(bv.x, bv.x);
            uint64_t bd1 = pack2(bv.y, bv.y);
            uint64_t bd2 = pack2(bv.z, bv.z);
            uint64_t bd3 = pack2(bv.w, bv.w);
            ffma2(acc2[0][0], av0.x, bd0); ffma2(acc2[1][0], av0.y, bd0);
            ffma2(acc2[2][0], av1.x, bd0); ffma2(acc2[3][0], av1.y, bd0);
            ffma2(acc2[0][1], av0.x, bd1); ffma2(acc2[1][1], av0.y, bd1);
            ffma2(acc2[2][1], av1.x, bd1); ffma2(acc2[3][1], av1.y, bd1);
            ffma2(acc2[0][2], av0.x, bd2); ffma2(acc2[1][2], av0.y, bd2);
            ffma2(acc2[2][2], av1.x, bd2); ffma2(acc2[3][2], av1.y, bd2);
            ffma2(acc2[0][3], av0.x, bd3); ffma2(acc2[1][3], av0.y, bd3);
            ffma2(acc2[2][3], av1.x, bd3); ffma2(acc2[3][3], av1.y, bd3);
        }
        __syncthreads();
    }

    // Unpack row pairs
    float acc[8][4];
    #pragma unroll
    for (int rp = 0; rp < 4; ++rp)
        #pragma unroll
        for (int c = 0; c < 4; ++c)
            unpack2(acc2[rp][c], acc[2*rp][c], acc[2*rp+1][c]);

    // Epilogue
    float bsum[4];
    #pragma unroll
    for (int c = 0; c < 4; ++c) {
        int col = c0 + cg + c;
        bsum[c] = bias1[col] + (bias2 ? bias2[col] : 0.f);
    }
    #pragma unroll
    for (int i = 0; i < 8; ++i) {
        long row = row0 + rbase + i;
        float4 o;
        o.x = acc[i][0] + bsum[0];
        o.y = acc[i][1] + bsum[1];
        o.z = acc[i][2] + bsum[2];
        o.w = acc[i][3] + bsum[3];
        if (RELU) {
            o.x = fmaxf(o.x, 0.f); o.y = fmaxf(o.y, 0.f);
            o.z = fmaxf(o.z, 0.f); o.w = fmaxf(o.w, 0.f);
        }
        *reinterpret_cast<float4*>(C + row * N + c0 + cg) = o;
    }
}

// ---------------------------------------------------------------------------
// OLD proven GEMM (kept for the small layers W2 / W3)
// ---------------------------------------------------------------------------
template<int KT, int NT, bool RELU>
__global__ void __launch_bounds__(256, 2) gemm_kernel(
    const float* __restrict__ A, const float* __restrict__ W,
    const float* __restrict__ bias1, const float* __restrict__ bias2,
    float* __restrict__ C, int N)
{
    constexpr int AP  = 68;
    constexpr int BP  = NT + 4;
    constexpr int KQ  = KT / 4;
    constexpr int CPT = NT / 32;

    extern __shared__ float smg[];
    float* As = smg;
    float* Bs = smg + KT * AP;

    const int  tid  = threadIdx.x;
    const long row0 = (long)blockIdx.x * 64;
    const int  c0   = blockIdx.y * NT;

    for (int idx = tid; idx < KQ * 64; idx += 256) {
        int kq = idx / 64, r = idx % 64;
        float4 v = *reinterpret_cast<const float4*>(A + (row0 + r) * KT + kq * 4);
        As[(kq*4+0)*AP + r] = v.x;
        As[(kq*4+1)*AP + r] = v.y;
        As[(kq*4+2)*AP + r] = v.z;
        As[(kq*4+3)*AP + r] = v.w;
    }
    for (int idx = tid; idx < KQ * NT; idx += 256) {
        int kq = idx / NT, jj = idx % NT;
        float4 v = *reinterpret_cast<const float4*>(W + (long)(c0 + jj) * KT + kq * 4);
        Bs[(kq*4+0)*BP + jj] = v.x;
        Bs[(kq*4+1)*BP + jj] = v.y;
        Bs[(kq*4+2)*BP + jj] = v.z;
        Bs[(kq*4+3)*BP + jj] = v.w;
    }
    __syncthreads();

    const int tx = tid & 31, ty = tid >> 5;
    uint64_t acc2[4][CPT];
    #pragma unroll
    for (int i2 = 0; i2 < 4; ++i2)
        #pragma unroll
        for (int c = 0; c < CPT; ++c) acc2[i2][c] = 0ull;

    #pragma unroll 8
    for (int k = 0; k < KT; ++k) {
        ulonglong2 av0 = *reinterpret_cast<const ulonglong2*>(&As[k * AP + ty * 8]);
        ulonglong2 av1 = *reinterpret_cast<const ulonglong2*>(&As[k * AP + ty * 8 + 4]);
        uint64_t ap[4] = {av0.x, av0.y, av1.x, av1.y};
        float bb[CPT];
        if constexpr (CPT == 4) {
            float4 bv = *reinterpret_cast<const float4*>(&Bs[k * BP + tx * 4]);
            bb[0] = bv.x; bb[1] = bv.y; bb[2] = bv.z; bb[3] = bv.w;
        } else {
            bb[0] = Bs[k * BP + tx];
        }
        #pragma unroll
        for (int c = 0; c < CPT; ++c) {
            uint64_t bd = pack2(bb[c], bb[c]);
            #pragma unroll
            for (int i2 = 0; i2 < 4; ++i2)
                ffma2(acc2[i2][c], ap[i2], bd);
        }
    }

    float acc[8][CPT];
    #pragma unroll
    for (int i2 = 0; i2 < 4; ++i2)
        #pragma unroll
        for (int c = 0; c < CPT; ++c)
            unpack2(acc2[i2][c], acc[2*i2][c], acc[2*i2+1][c]);

    if constexpr (CPT == 4) {
        float bsum[4];
        #pragma unroll
        for (int c = 0; c < 4; ++c) {
            int col = c0 + tx * 4 + c;
            bsum[c] = bias1[col] + (bias2 ? bias2[col] : 0.f);
        }
        #pragma unroll
        for (int i = 0; i < 8; ++i) {
            long row = row0 + ty * 8 + i;
            float4 o;
            o.x = acc[i][0] + bsum[0];
            o.y = acc[i][1] + bsum[1];
            o.z = acc[i][2] + bsum[2];
            o.w = acc[i][3] + bsum[3];
            if (RELU) {
                o.x = fmaxf(o.x, 0.f); o.y = fmaxf(o.y, 0.f);
                o.z = fmaxf(o.z, 0.f); o.w = fmaxf(o.w, 0.f);
            }
            *reinterpret_cast<float4*>(C + row * N + c0 + tx * 4) = o;
        }
    } else {
        int col = c0 + tx;
        float bsum = bias1[col] + (bias2 ? bias2[col] : 0.f);
        #pragma unroll
        for (int i = 0; i < 8; ++i) {
            long row = row0 + ty * 8 + i;
            float v = acc[i][0] + bsum;
            if (RELU) v = fmaxf(v, 0.f);
            C[row * N + col] = v;
        }
    }
}

// ---------------------------------------------------------------------------
// Persistent LSTM recurrence + heads (R10 best + 3rd barrier removed:
// heads read only hbuf/WaCs/bac; next phase A writes only gbuf/ms[nslot],
// all hazards covered by barriers 1-2).
// ---------------------------------------------------------------------------
#define OFF_WSH   0                         // 512*128 half   = 131072
#define OFF_HBUF  131072                    // 8*128 f32      =   4096
#define OFF_CBUF  135168                    //                =   4096
#define OFF_HP    139264                    // 4*128 float2   =   4096
#define OFF_GBUF  143360                    // 512*9 f32      =  18432
#define OFF_WAC   161792                    // 19*132 f32     =  10048 (pad)
#define OFF_BAC   171840                    // 19 f32         =     80 (pad)
#define OFF_MS    171920                    // 2*8 f32        =     64
#define SMEM_LSTM 171984

__global__ void __launch_bounds__(512, 1) lstm_kernel(
    const float* __restrict__ Z,    const float* __restrict__ done,
    const float* __restrict__ h0,   const float* __restrict__ c0,
    const float* __restrict__ Whh,
    const float* __restrict__ Wa,   const float* __restrict__ ba,
    const float* __restrict__ Wc,   const float* __restrict__ bc,
    float* __restrict__ out)
{
    extern __shared__ char smraw[];
    __half*  wsh  = reinterpret_cast<__half*>(smraw + OFF_WSH);
    float*   hbuf = reinterpret_cast<float*>(smraw + OFF_HBUF);
    float*   cbuf = reinterpret_cast<float*>(smraw + OFF_CBUF);
    float2*  hp   = reinterpret_cast<float2*>(smraw + OFF_HP);
    float*   gbuf = reinterpret_cast<float*>(smraw + OFF_GBUF);
    float*   WaCs = reinterpret_cast<float*>(smraw + OFF_WAC);
    float*   bac  = reinterpret_cast<float*>(smraw + OFF_BAC);
    float*   ms   = reinterpret_cast<float*>(smraw + OFF_MS);

    const int tid = threadIdx.x;
    const int gb0 = blockIdx.x * 8;        // 128 CTAs x 8 lanes = 1024

    for (int idx = tid; idx < 512 * 128; idx += 512) {
        int jj = idx >> 7, k = idx & 127;
        wsh[((k >> 2) << 11) + (jj << 2) + (k & 3)] = __float2half(Whh[idx]);
    }
    for (int idx = tid; idx < 8 * 128; idx += 512) {
        int b = idx >> 7, u = idx & 127;
        hbuf[idx] = h0[(gb0 + b) * HH + u];
        cbuf[idx] = c0[(gb0 + b) * HH + u];
    }
    for (int idx = tid; idx < 4 * 128; idx += 512) {
        int p = idx >> 7, k = idx & 127;
        hp[p * 128 + k] = make_float2(h0[(gb0 + 2*p) * HH + k],
                                      h0[(gb0 + 2*p + 1) * HH + k]);
    }
    for (int idx = tid; idx < 19 * 128; idx += 512) {
        int a = idx >> 7, k = idx & 127;
        WaCs[a * 132 + k] = (a < 18) ? Wa[a * 128 + k] : Wc[k];
    }
    if (tid < 19) bac[tid] = (tid < 18) ? ba[tid] : bc[0];
    if (tid < 8)  ms[tid]  = 1.f - done[gb0 + tid];
    __syncthreads();

    const int j    = tid;
    const int type = j >> 7;

    for (int t = 0; t < TT; ++t) {
        const int slot  = (t & 1) * 8;
        const int nslot = ((t + 1) & 1) * 8;

        float zr[8];
        const long zbase = ((long)t * BB + gb0) * 512 + j;
        #pragma unroll
        for (int b = 0; b < 8; ++b)
            zr[b] = Z[zbase + (long)b * 512];
        float dn = 0.f;
        if (tid < 8)
            dn = (t < TT - 1) ? done[(t + 1) * BB + gb0 + tid] : 0.f;
        float mk[8];
        #pragma unroll
        for (int b = 0; b < 8; ++b) mk[b] = ms[slot + b];

        uint64_t acc2[4] = {0ull, 0ull, 0ull, 0ull};
        #pragma unroll 4
        for (int k4 = 0; k4 < 32; ++k4) {
            uint2 wr = *reinterpret_cast<const uint2*>(wsh + (k4 << 11) + (j << 2));
            float2 w01 = __half22float2(*reinterpret_cast<const __half2*>(&wr.x));
            float2 w23 = __half22float2(*reinterpret_cast<const __half2*>(&wr.y));
            uint64_t wd0 = pack2(w01.x, w01.x);
            uint64_t wd1 = pack2(w01.y, w01.y);
            uint64_t wd2 = pack2(w23.x, w23.x);
            uint64_t wd3 = pack2(w23.y, w23.y);
            ulonglong2 ha[4], hb[4];
            #pragma unroll
            for (int p = 0; p < 4; ++p) {
                ha[p] = *reinterpret_cast<const ulonglong2*>(&hp[(p << 7) + (k4 << 2)]);
                hb[p] = *reinterpret_cast<const ulonglong2*>(&hp[(p << 7) + (k4 << 2) + 2]);
            }
            #pragma unroll
            for (int p = 0; p < 4; ++p) ffma2(acc2[p], wd0, ha[p].x);
            #pragma unroll
            for (int p = 0; p < 4; ++p) ffma2(acc2[p], wd1, ha[p].y);
            #pragma unroll
            for (int p = 0; p < 4; ++p) ffma2(acc2[p], wd2, hb[p].x);
            #pragma unroll
            for (int p = 0; p < 4; ++p) ffma2(acc2[p], wd3, hb[p].y);
        }
        float av[8];
        #pragma unroll
        for (int p = 0; p < 4; ++p) unpack2(acc2[p], av[2*p], av[2*p+1]);
        #pragma unroll
        for (int b = 0; b < 8; ++b) {
            float v = fmaf(av[b], mk[b], zr[b]);
            float gv = (type == 2) ? tanh_fast(v) : sigm_fast(v);
            gbuf[j * 9 + b] = gv;
        }
        if (tid < 8) ms[nslot + tid] = 1.f - dn;
        __syncthreads();                       // BARRIER 1

        #pragma unroll
        for (int it = 0; it < 2; ++it) {
            int idx = tid + it * 512;
            int b = idx >> 7, u = idx & 127;
            float m = ms[slot + b];
            int gbase = u * 9 + b;
            float iv = gbuf[gbase];
            float fv = gbuf[gbase + 128 * 9];
            float gg = gbuf[gbase + 256 * 9];
            float ov = gbuf[gbase + 384 * 9];
            float cv = fmaf(fv, cbuf[idx] * m, iv * gg);
            float hv = ov * tanh_fast(cv);
            cbuf[idx] = cv;
            hbuf[idx] = hv;
            reinterpret_cast<float*>(hp)[(((b >> 1) << 7) + u) * 2 + (b & 1)] = hv;
        }
        __syncthreads();                       // BARRIER 2

        if (tid < 8 * 19) {
            int b = tid / 19, a = tid - b * 19;
            float s0 = 0.f, s1 = 0.f;
            #pragma unroll 4
            for (int k8 = 0; k8 < 16; ++k8) {
                float4 w0 = *reinterpret_cast<const float4*>(&WaCs[a * 132 + k8 * 8]);
                float4 w1 = *reinterpret_cast<const float4*>(&WaCs[a * 132 + k8 * 8 + 4]);
                float4 hv0 = *reinterpret_cast<const float4*>(&hbuf[b * 128 + k8 * 8]);
                float4 hv1 = *reinterpret_cast<const float4*>(&hbuf[b * 128 + k8 * 8 + 4]);
                s0 = fmaf(w0.x, hv0.x, s0); s0 = fmaf(w0.y, hv0.y, s0);
                s0 = fmaf(w0.z, hv0.z, s0); s0 = fmaf(w0.w, hv0.w, s0);
                s1 = fmaf(w1.x, hv1.x, s1); s1 = fmaf(w1.y, hv1.y, s1);
                s1 = fmaf(w1.z, hv1.z, s1); s1 = fmaf(w1.w, hv1.w, s1);
            }
            out[((long)t * BB + gb0 + b) * 19 + a] = s0 + s1 + bac[a];
        }
        // (3rd barrier removed — no hazard: heads read hbuf/WaCs only,
        //  next phase A writes gbuf/ms[nslot] only, hbuf rewritten after B1.)
    }
}

// ---------------------------------------------------------------------------
// Host launcher
// ---------------------------------------------------------------------------
extern "C" void kernel_launch(void* const* d_in, const int* in_sizes, int n_in,
                              void* d_out, int out_size)
{
    const float* x    = (const float*)d_in[0];
    const float* done = (const float*)d_in[1];
    const float* h0   = (const float*)d_in[2];
    const float* c0   = (const float*)d_in[3];
    const float* W1   = (const float*)d_in[4];
    const float* b1   = (const float*)d_in[5];
    const float* W2   = (const float*)d_in[6];
    const float* b2   = (const float*)d_in[7];
    const float* W3   = (const float*)d_in[8];
    const float* b3   = (const float*)d_in[9];
    const float* Wih  = (const float*)d_in[10];
    const float* Whh  = (const float*)d_in[11];
    const float* bih  = (const float*)d_in[12];
    const float* bhh  = (const float*)d_in[13];
    const float* Wa   = (const float*)d_in[14];
    const float* ba   = (const float*)d_in[15];
    const float* Wc   = (const float*)d_in[16];
    const float* bc   = (const float*)d_in[17];
    float* out = (float*)d_out;

    float *h1p, *h2p, *h3p, *Zp;
    cudaGetSymbolAddress((void**)&h1p, g_h1);
    cudaGetSymbolAddress((void**)&h2p, g_h2);
    cudaGetSymbolAddress((void**)&h3p, g_h3);
    cudaGetSymbolAddress((void**)&Zp,  g_Z);

    const int S_B2      = (64 * 128 + 64 * 132) * 4;    //  66560 (2 CTAs/SM)
    const int S_128_32  = (128 * 68 + 128 * 36) * 4;    //  53248
    const int S_32_128  = (32  * 68 + 32  * 132) * 4;   //  25600

    cudaFuncSetAttribute(gemm_b2<128, true>,
                         cudaFuncAttributeMaxDynamicSharedMemorySize, S_B2);
    cudaFuncSetAttribute(gemm_b2<128, false>,
                         cudaFuncAttributeMaxDynamicSharedMemorySize, S_B2);
    cudaFuncSetAttribute(gemm_kernel<128, 32, true>,
                         cudaFuncAttributeMaxDynamicSharedMemorySize, S_128_32);
    cudaFuncSetAttribute(gemm_kernel<32, 128, true>,
                         cudaFuncAttributeMaxDynamicSharedMemorySize, S_32_128);
    cudaFuncSetAttribute(lstm_kernel,
                         cudaFuncAttributeMaxDynamicSharedMemorySize, SMEM_LSTM);

    const int NB128 = MROWS / 128;  // 2048 (gemm_b2 row tiles)
    const int NB64  = MROWS / 64;   // 4096 (old kernel row tiles)

    // Encoder
    gemm_b2<128, true><<<dim3(NB128, 1), 512, S_B2>>>(
        x,   W1, b1, nullptr, h1p, 128);
    gemm_kernel<128, 32, true><<<dim3(NB64, 1), 256, S_128_32>>>(
        h1p, W2, b2, nullptr, h2p, 32);
    gemm_kernel<32, 128, true><<<dim3(NB64, 1), 256, S_32_128>>>(
        h2p, W3, b3, nullptr, h3p, 128);
    // Input projection: Z = hid @ Wih^T + bih + bhh  (N=512, 4 col tiles)
    gemm_b2<128, false><<<dim3(NB128, 4), 512, S_B2>>>(
        h3p, Wih, bih, bhh, Zp, 512);

    // Recurrence + heads
    lstm_kernel<<<128, 512, SMEM_LSTM>>>(
        Zp, done, h0, c0, Whh, Wa, ba, Wc, bc, out);
}

// round 16
// speedup vs baseline: 1.0343x; 1.0343x over previous
#include <cuda_runtime.h>
#include <cuda_fp16.h>
#include <cuda_bf16.h>
#include <cstdint>

// Problem constants
#define TT 256
#define BB 1024
#define OBS 128
#define LS 128
#define HH 128
#define NA 18
#define MROWS (TT*BB)          // 262144

// ---------------------------------------------------------------------------
// Scratch (device globals; no cudaMalloc allowed)
// ---------------------------------------------------------------------------
__device__ float g_h1[(size_t)MROWS * 128];   // encoder layer-1 out
__device__ float g_h2[(size_t)MROWS * 32];    // encoder layer-2 out
__device__ float g_h3[(size_t)MROWS * 128];   // encoder layer-3 out
__device__ float g_Z [(size_t)MROWS * 512];   // precomputed input gates + biases

// ---------------------------------------------------------------------------
// f32x2 packed-FMA helpers (exact fp32 math; 2 MACs per issued inst)
// ---------------------------------------------------------------------------
__device__ __forceinline__ void ffma2(uint64_t& acc, uint64_t a, uint64_t b) {
    asm("fma.rn.f32x2 %0, %1, %2, %0;" : "+l"(acc) : "l"(a), "l"(b));
}
__device__ __forceinline__ uint64_t pack2(float x, float y) {
    uint64_t r;
    asm("mov.b64 %0, {%1, %2};" : "=l"(r) : "f"(x), "f"(y));
    return r;
}
__device__ __forceinline__ void unpack2(uint64_t v, float& lo, float& hi) {
    asm("mov.b64 {%0, %1}, %2;" : "=f"(lo), "=f"(hi) : "l"(v));
}

// ---------------------------------------------------------------------------
// Fast nonlinearities (MUFU; fma pipe stays free)
// ---------------------------------------------------------------------------
__device__ __forceinline__ float sigm_fast(float x) {
    x = fminf(fmaxf(x, -30.f), 30.f);
    return __fdividef(1.f, 1.f + __expf(-x));
}
__device__ __forceinline__ float tanh_fast(float x) {
    x = fminf(fmaxf(x, -15.f), 15.f);
    float e = __expf(-2.f * x);
    return __fdividef(1.f - e, 1.f + e);
}

// ---------------------------------------------------------------------------
// NEW: 2-CTA/SM, full-intensity GEMM.
// 256 threads (8 warps), tile 64 x NT (NT = 128 or 256), K staged in
// 64-chunks. smem = 50-83 KB/CTA and <=128 regs -> 2 CTAs resident/SM:
// one CTA's staging/latency stalls are covered by the other's FFMA2 math.
// Per warp-k (NT=256): 2 broadcast A-LDS + 2 contiguous B-LDS.128 (10 wf)
// vs 32 FFMA2 (16 cyc) -> fma-bound.
//   C[M][NT-tile] = act( A[M][K] @ W[N][K]^T + b1 (+b2) )
// ---------------------------------------------------------------------------
template<int KT, int NT, bool RELU>
__global__ void __launch_bounds__(256, 2) gemm_b3(
    const float* __restrict__ A, const float* __restrict__ W,
    const float* __restrict__ bias1, const float* __restrict__ bias2,
    float* __restrict__ C, int N)
{
    constexpr int BP  = NT + 4;     // padded B leading dim
    constexpr int CPT = NT / 32;    // cols per thread (8 or 4)
    constexpr int NG  = CPT / 4;    // float4 groups per thread (2 or 1)

    extern __shared__ float smg[];
    float* As = smg;                // 64 k x 64 rows
    float* Bs = smg + 64 * 64;      // 64 k x BP

    const int  tid   = threadIdx.x;
    const int  lane  = tid & 31;
    const int  wid   = tid >> 5;        // 0..7
    const int  rbase = wid * 8;
    const int  cg    = lane * 4;
    const long row0  = (long)blockIdx.x * 64;
    const int  c0    = blockIdx.y * NT;

    uint64_t acc2[4][CPT];
    #pragma unroll
    for (int rp = 0; rp < 4; ++rp)
        #pragma unroll
        for (int c = 0; c < CPT; ++c) acc2[rp][c] = 0ull;

    for (int kc = 0; kc < KT; kc += 64) {
        // Stage A chunk transposed: As[k][row], 64 rows x 64 k
        for (int idx = tid; idx < 16 * 64; idx += 256) {
            int kq = idx >> 6, r = idx & 63;
            float4 v = *reinterpret_cast<const float4*>(
                A + (row0 + r) * KT + kc + kq * 4);
            As[(kq*4+0)*64 + r] = v.x;
            As[(kq*4+1)*64 + r] = v.y;
            As[(kq*4+2)*64 + r] = v.z;
            As[(kq*4+3)*64 + r] = v.w;
        }
        // Stage B chunk transposed: Bs[k][col], NT cols x 64 k
        for (int idx = tid; idx < 16 * NT; idx += 256) {
            int kq = idx / NT, jj = idx % NT;
            float4 v = *reinterpret_cast<const float4*>(
                W + (long)(c0 + jj) * KT + kc + kq * 4);
            Bs[(kq*4+0)*BP + jj] = v.x;
            Bs[(kq*4+1)*BP + jj] = v.y;
            Bs[(kq*4+2)*BP + jj] = v.z;
            Bs[(kq*4+3)*BP + jj] = v.w;
        }
        __syncthreads();

        #pragma unroll 4
        for (int k = 0; k < 64; ++k) {
            // A fragment: 8 rows, warp-uniform broadcast (2x LDS.128)
            ulonglong2 av0 = *reinterpret_cast<const ulonglong2*>(&As[k * 64 + rbase]);
            ulonglong2 av1 = *reinterpret_cast<const ulonglong2*>(&As[k * 64 + rbase + 4]);
            uint64_t ap[4] = {av0.x, av0.y, av1.x, av1.y};
            // B fragment: NG coalesced float4 loads (512B contiguous per warp)
            float bb[CPT];
            #pragma unroll
            for (int g = 0; g < NG; ++g) {
                float4 bv = *reinterpret_cast<const float4*>(&Bs[k * BP + g * 128 + cg]);
                bb[g*4+0] = bv.x; bb[g*4+1] = bv.y; bb[g*4+2] = bv.z; bb[g*4+3] = bv.w;
            }
            #pragma unroll
            for (int c = 0; c < CPT; ++c) {
                uint64_t bd = pack2(bb[c], bb[c]);
                #pragma unroll
                for (int rp = 0; rp < 4; ++rp)
                    ffma2(acc2[rp][c], ap[rp], bd);
            }
        }
        __syncthreads();
    }

    // Unpack row pairs
    float acc[8][CPT];
    #pragma unroll
    for (int rp = 0; rp < 4; ++rp)
        #pragma unroll
        for (int c = 0; c < CPT; ++c)
            unpack2(acc2[rp][c], acc[2*rp][c], acc[2*rp+1][c]);

    // Epilogue (per-group contiguous columns)
    float bsum[CPT];
    #pragma unroll
    for (int g = 0; g < NG; ++g)
        #pragma unroll
        for (int c = 0; c < 4; ++c) {
            int col = c0 + g * 128 + cg + c;
            bsum[g*4+c] = bias1[col] + (bias2 ? bias2[col] : 0.f);
        }
    #pragma unroll
    for (int i = 0; i < 8; ++i) {
        long row = row0 + rbase + i;
        #pragma unroll
        for (int g = 0; g < NG; ++g) {
            float4 o;
            o.x = acc[i][g*4+0] + bsum[g*4+0];
            o.y = acc[i][g*4+1] + bsum[g*4+1];
            o.z = acc[i][g*4+2] + bsum[g*4+2];
            o.w = acc[i][g*4+3] + bsum[g*4+3];
            if (RELU) {
                o.x = fmaxf(o.x, 0.f); o.y = fmaxf(o.y, 0.f);
                o.z = fmaxf(o.z, 0.f); o.w = fmaxf(o.w, 0.f);
            }
            *reinterpret_cast<float4*>(C + row * N + c0 + g * 128 + cg) = o;
        }
    }
}

// ---------------------------------------------------------------------------
// OLD proven GEMM (kept for the small layers W2 / W3)
// ---------------------------------------------------------------------------
template<int KT, int NT, bool RELU>
__global__ void __launch_bounds__(256, 2) gemm_kernel(
    const float* __restrict__ A, const float* __restrict__ W,
    const float* __restrict__ bias1, const float* __restrict__ bias2,
    float* __restrict__ C, int N)
{
    constexpr int AP  = 68;
    constexpr int BP  = NT + 4;
    constexpr int KQ  = KT / 4;
    constexpr int CPT = NT / 32;

    extern __shared__ float smg[];
    float* As = smg;
    float* Bs = smg + KT * AP;

    const int  tid  = threadIdx.x;
    const long row0 = (long)blockIdx.x * 64;
    const int  c0   = blockIdx.y * NT;

    for (int idx = tid; idx < KQ * 64; idx += 256) {
        int kq = idx / 64, r = idx % 64;
        float4 v = *reinterpret_cast<const float4*>(A + (row0 + r) * KT + kq * 4);
        As[(kq*4+0)*AP + r] = v.x;
        As[(kq*4+1)*AP + r] = v.y;
        As[(kq*4+2)*AP + r] = v.z;
        As[(kq*4+3)*AP + r] = v.w;
    }
    for (int idx = tid; idx < KQ * NT; idx += 256) {
        int kq = idx / NT, jj = idx % NT;
        float4 v = *reinterpret_cast<const float4*>(W + (long)(c0 + jj) * KT + kq * 4);
        Bs[(kq*4+0)*BP + jj] = v.x;
        Bs[(kq*4+1)*BP + jj] = v.y;
        Bs[(kq*4+2)*BP + jj] = v.z;
        Bs[(kq*4+3)*BP + jj] = v.w;
    }
    __syncthreads();

    const int tx = tid & 31, ty = tid >> 5;
    uint64_t acc2[4][CPT];
    #pragma unroll
    for (int i2 = 0; i2 < 4; ++i2)
        #pragma unroll
        for (int c = 0; c < CPT; ++c) acc2[i2][c] = 0ull;

    #pragma unroll 8
    for (int k = 0; k < KT; ++k) {
        ulonglong2 av0 = *reinterpret_cast<const ulonglong2*>(&As[k * AP + ty * 8]);
        ulonglong2 av1 = *reinterpret_cast<const ulonglong2*>(&As[k * AP + ty * 8 + 4]);
        uint64_t ap[4] = {av0.x, av0.y, av1.x, av1.y};
        float bb[CPT];
        if constexpr (CPT == 4) {
            float4 bv = *reinterpret_cast<const float4*>(&Bs[k * BP + tx * 4]);
            bb[0] = bv.x; bb[1] = bv.y; bb[2] = bv.z; bb[3] = bv.w;
        } else {
            bb[0] = Bs[k * BP + tx];
        }
        #pragma unroll
        for (int c = 0; c < CPT; ++c) {
            uint64_t bd = pack2(bb[c], bb[c]);
            #pragma unroll
            for (int i2 = 0; i2 < 4; ++i2)
                ffma2(acc2[i2][c], ap[i2], bd);
        }
    }

    float acc[8][CPT];
    #pragma unroll
    for (int i2 = 0; i2 < 4; ++i2)
        #pragma unroll
        for (int c = 0; c < CPT; ++c)
            unpack2(acc2[i2][c], acc[2*i2][c], acc[2*i2+1][c]);

    if constexpr (CPT == 4) {
        float bsum[4];
        #pragma unroll
        for (int c = 0; c < 4; ++c) {
            int col = c0 + tx * 4 + c;
            bsum[c] = bias1[col] + (bias2 ? bias2[col] : 0.f);
        }
        #pragma unroll
        for (int i = 0; i < 8; ++i) {
            long row = row0 + ty * 8 + i;
            float4 o;
            o.x = acc[i][0] + bsum[0];
            o.y = acc[i][1] + bsum[1];
            o.z = acc[i][2] + bsum[2];
            o.w = acc[i][3] + bsum[3];
            if (RELU) {
                o.x = fmaxf(o.x, 0.f); o.y = fmaxf(o.y, 0.f);
                o.z = fmaxf(o.z, 0.f); o.w = fmaxf(o.w, 0.f);
            }
            *reinterpret_cast<float4*>(C + row * N + c0 + tx * 4) = o;
        }
    } else {
        int col = c0 + tx;
        float bsum = bias1[col] + (bias2 ? bias2[col] : 0.f);
        #pragma unroll
        for (int i = 0; i < 8; ++i) {
            long row = row0 + ty * 8 + i;
            float v = acc[i][0] + bsum;
            if (RELU) v = fmaxf(v, 0.f);
            C[row * N + col] = v;
        }
    }
}

// ---------------------------------------------------------------------------
// Persistent LSTM recurrence + heads (proven config; 3rd barrier removed —
// heads read only hbuf/WaCs/bac; next phase A writes only gbuf/ms[nslot]).
// 128 CTAs x 512 threads; 8 lanes/CTA; Whh fp16 smem; f32x2 matvec.
// ---------------------------------------------------------------------------
#define OFF_WSH   0                         // 512*128 half   = 131072
#define OFF_HBUF  131072                    // 8*128 f32      =   4096
#define OFF_CBUF  135168                    //                =   4096
#define OFF_HP    139264                    // 4*128 float2   =   4096
#define OFF_GBUF  143360                    // 512*9 f32      =  18432
#define OFF_WAC   161792                    // 19*132 f32     =  10048 (pad)
#define OFF_BAC   171840                    // 19 f32         =     80 (pad)
#define OFF_MS    171920                    // 2*8 f32        =     64
#define SMEM_LSTM 171984

__global__ void __launch_bounds__(512, 1) lstm_kernel(
    const float* __restrict__ Z,    const float* __restrict__ done,
    const float* __restrict__ h0,   const float* __restrict__ c0,
    const float* __restrict__ Whh,
    const float* __restrict__ Wa,   const float* __restrict__ ba,
    const float* __restrict__ Wc,   const float* __restrict__ bc,
    float* __restrict__ out)
{
    extern __shared__ char smraw[];
    __half*  wsh  = reinterpret_cast<__half*>(smraw + OFF_WSH);
    float*   hbuf = reinterpret_cast<float*>(smraw + OFF_HBUF);
    float*   cbuf = reinterpret_cast<float*>(smraw + OFF_CBUF);
    float2*  hp   = reinterpret_cast<float2*>(smraw + OFF_HP);
    float*   gbuf = reinterpret_cast<float*>(smraw + OFF_GBUF);
    float*   WaCs = reinterpret_cast<float*>(smraw + OFF_WAC);
    float*   bac  = reinterpret_cast<float*>(smraw + OFF_BAC);
    float*   ms   = reinterpret_cast<float*>(smraw + OFF_MS);

    const int tid = threadIdx.x;
    const int gb0 = blockIdx.x * 8;        // 128 CTAs x 8 lanes = 1024

    for (int idx = tid; idx < 512 * 128; idx += 512) {
        int jj = idx >> 7, k = idx & 127;
        wsh[((k >> 2) << 11) + (jj << 2) + (k & 3)] = __float2half(Whh[idx]);
    }
    for (int idx = tid; idx < 8 * 128; idx += 512) {
        int b = idx >> 7, u = idx & 127;
        hbuf[idx] = h0[(gb0 + b) * HH + u];
        cbuf[idx] = c0[(gb0 + b) * HH + u];
    }
    for (int idx = tid; idx < 4 * 128; idx += 512) {
        int p = idx >> 7, k = idx & 127;
        hp[p * 128 + k] = make_float2(h0[(gb0 + 2*p) * HH + k],
                                      h0[(gb0 + 2*p + 1) * HH + k]);
    }
    for (int idx = tid; idx < 19 * 128; idx += 512) {
        int a = idx >> 7, k = idx & 127;
        WaCs[a * 132 + k] = (a < 18) ? Wa[a * 128 + k] : Wc[k];
    }
    if (tid < 19) bac[tid] = (tid < 18) ? ba[tid] : bc[0];
    if (tid < 8)  ms[tid]  = 1.f - done[gb0 + tid];
    __syncthreads();

    const int j    = tid;
    const int type = j >> 7;

    for (int t = 0; t < TT; ++t) {
        const int slot  = (t & 1) * 8;
        const int nslot = ((t + 1) & 1) * 8;

        float zr[8];
        const long zbase = ((long)t * BB + gb0) * 512 + j;
        #pragma unroll
        for (int b = 0; b < 8; ++b)
            zr[b] = Z[zbase + (long)b * 512];
        float dn = 0.f;
        if (tid < 8)
            dn = (t < TT - 1) ? done[(t + 1) * BB + gb0 + tid] : 0.f;
        float mk[8];
        #pragma unroll
        for (int b = 0; b < 8; ++b) mk[b] = ms[slot + b];

        uint64_t acc2[4] = {0ull, 0ull, 0ull, 0ull};
        #pragma unroll 4
        for (int k4 = 0; k4 < 32; ++k4) {
            uint2 wr = *reinterpret_cast<const uint2*>(wsh + (k4 << 11) + (j << 2));
            float2 w01 = __half22float2(*reinterpret_cast<const __half2*>(&wr.x));
            float2 w23 = __half22float2(*reinterpret_cast<const __half2*>(&wr.y));
            uint64_t wd0 = pack2(w01.x, w01.x);
            uint64_t wd1 = pack2(w01.y, w01.y);
            uint64_t wd2 = pack2(w23.x, w23.x);
            uint64_t wd3 = pack2(w23.y, w23.y);
            ulonglong2 ha[4], hb[4];
            #pragma unroll
            for (int p = 0; p < 4; ++p) {
                ha[p] = *reinterpret_cast<const ulonglong2*>(&hp[(p << 7) + (k4 << 2)]);
                hb[p] = *reinterpret_cast<const ulonglong2*>(&hp[(p << 7) + (k4 << 2) + 2]);
            }
            #pragma unroll
            for (int p = 0; p < 4; ++p) ffma2(acc2[p], wd0, ha[p].x);
            #pragma unroll
            for (int p = 0; p < 4; ++p) ffma2(acc2[p], wd1, ha[p].y);
            #pragma unroll
            for (int p = 0; p < 4; ++p) ffma2(acc2[p], wd2, hb[p].x);
            #pragma unroll
            for (int p = 0; p < 4; ++p) ffma2(acc2[p], wd3, hb[p].y);
        }
        float av[8];
        #pragma unroll
        for (int p = 0; p < 4; ++p) unpack2(acc2[p], av[2*p], av[2*p+1]);
        #pragma unroll
        for (int b = 0; b < 8; ++b) {
            float v = fmaf(av[b], mk[b], zr[b]);
            float gv = (type == 2) ? tanh_fast(v) : sigm_fast(v);
            gbuf[j * 9 + b] = gv;
        }
        if (tid < 8) ms[nslot + tid] = 1.f - dn;
        __syncthreads();                       // BARRIER 1

        #pragma unroll
        for (int it = 0; it < 2; ++it) {
            int idx = tid + it * 512;
            int b = idx >> 7, u = idx & 127;
            float m = ms[slot + b];
            int gbase = u * 9 + b;
            float iv = gbuf[gbase];
            float fv = gbuf[gbase + 128 * 9];
            float gg = gbuf[gbase + 256 * 9];
            float ov = gbuf[gbase + 384 * 9];
            float cv = fmaf(fv, cbuf[idx] * m, iv * gg);
            float hv = ov * tanh_fast(cv);
            cbuf[idx] = cv;
            hbuf[idx] = hv;
            reinterpret_cast<float*>(hp)[(((b >> 1) << 7) + u) * 2 + (b & 1)] = hv;
        }
        __syncthreads();                       // BARRIER 2

        if (tid < 8 * 19) {
            int b = tid / 19, a = tid - b * 19;
            float s0 = 0.f, s1 = 0.f;
            #pragma unroll 4
            for (int k8 = 0; k8 < 16; ++k8) {
                float4 w0 = *reinterpret_cast<const float4*>(&WaCs[a * 132 + k8 * 8]);
                float4 w1 = *reinterpret_cast<const float4*>(&WaCs[a * 132 + k8 * 8 + 4]);
                float4 hv0 = *reinterpret_cast<const float4*>(&hbuf[b * 128 + k8 * 8]);
                float4 hv1 = *reinterpret_cast<const float4*>(&hbuf[b * 128 + k8 * 8 + 4]);
                s0 = fmaf(w0.x, hv0.x, s0); s0 = fmaf(w0.y, hv0.y, s0);
                s0 = fmaf(w0.z, hv0.z, s0); s0 = fmaf(w0.w, hv0.w, s0);
                s1 = fmaf(w1.x, hv1.x, s1); s1 = fmaf(w1.y, hv1.y, s1);
                s1 = fmaf(w1.z, hv1.z, s1); s1 = fmaf(w1.w, hv1.w, s1);
            }
            out[((long)t * BB + gb0 + b) * 19 + a] = s0 + s1 + bac[a];
        }
        // (3rd barrier removed — no hazard: heads read hbuf/WaCs only,
        //  next phase A writes gbuf/ms[nslot] only.)
    }
}

// ---------------------------------------------------------------------------
// Host launcher
// ---------------------------------------------------------------------------
extern "C" void kernel_launch(void* const* d_in, const int* in_sizes, int n_in,
                              void* d_out, int out_size)
{
    const float* x    = (const float*)d_in[0];
    const float* done = (const float*)d_in[1];
    const float* h0   = (const float*)d_in[2];
    const float* c0   = (const float*)d_in[3];
    const float* W1   = (const float*)d_in[4];
    const float* b1   = (const float*)d_in[5];
    const float* W2   = (const float*)d_in[6];
    const float* b2   = (const float*)d_in[7];
    const float* W3   = (const float*)d_in[8];
    const float* b3   = (const float*)d_in[9];
    const float* Wih  = (const float*)d_in[10];
    const float* Whh  = (const float*)d_in[11];
    const float* bih  = (const float*)d_in[12];
    const float* bhh  = (const float*)d_in[13];
    const float* Wa   = (const float*)d_in[14];
    const float* ba   = (const float*)d_in[15];
    const float* Wc   = (const float*)d_in[16];
    const float* bc   = (const float*)d_in[17];
    float* out = (float*)d_out;

    float *h1p, *h2p, *h3p, *Zp;
    cudaGetSymbolAddress((void**)&h1p, g_h1);
    cudaGetSymbolAddress((void**)&h2p, g_h2);
    cudaGetSymbolAddress((void**)&h3p, g_h3);
    cudaGetSymbolAddress((void**)&Zp,  g_Z);

    // gemm_b3 smem: As 64*64 + Bs 64*(NT+4), fp32 (2 CTAs/SM)
    const int S_B3_256 = (64 * 64 + 64 * 260) * 4;   //  82944
    const int S_B3_128 = (64 * 64 + 64 * 132) * 4;   //  50176
    // old-kernel smem
    const int S_128_32 = (128 * 68 + 128 * 36) * 4;  //  53248
    const int S_32_128 = (32  * 68 + 32 * 132) * 4;  //  25600

    cudaFuncSetAttribute(gemm_b3<128, 128, true>,
                         cudaFuncAttributeMaxDynamicSharedMemorySize, S_B3_128);
    cudaFuncSetAttribute(gemm_b3<128, 256, false>,
                         cudaFuncAttributeMaxDynamicSharedMemorySize, S_B3_256);
    cudaFuncSetAttribute(gemm_kernel<128, 32, true>,
                         cudaFuncAttributeMaxDynamicSharedMemorySize, S_128_32);
    cudaFuncSetAttribute(gemm_kernel<32, 128, true>,
                         cudaFuncAttributeMaxDynamicSharedMemorySize, S_32_128);
    cudaFuncSetAttribute(lstm_kernel,
                         cudaFuncAttributeMaxDynamicSharedMemorySize, SMEM_LSTM);

    const int NB64 = MROWS / 64;   // 4096 row tiles

    // Encoder
    gemm_b3<128, 128, true><<<dim3(NB64, 1), 256, S_B3_128>>>(
        x,   W1, b1, nullptr, h1p, 128);
    gemm_kernel<128, 32, true><<<dim3(NB64, 1), 256, S_128_32>>>(
        h1p, W2, b2, nullptr, h2p, 32);
    gemm_kernel<32, 128, true><<<dim3(NB64, 1), 256, S_32_128>>>(
        h2p, W3, b3, nullptr, h3p, 128);
    // Input projection: Z = hid @ Wih^T + bih + bhh  (N=512, 2 col tiles of 256)
    gemm_b3<128, 256, false><<<dim3(NB64, 2), 256, S_B3_256>>>(
        h3p, Wih, bih, bhh, Zp, 512);

    // Recurrence + heads
    lstm_kernel<<<128, 512, SMEM_LSTM>>>(
        Zp, done, h0, c0, Whh, Wa, ba, Wc, bc, out);
}

// round 17
// speedup vs baseline: 1.0539x; 1.0190x over previous
#include <cuda_runtime.h>
#include <cuda_fp16.h>
#include <cuda_bf16.h>
#include <cstdint>

// Problem constants
#define TT 256
#define BB 1024
#define OBS 128
#define LS 128
#define HH 128
#define NA 18
#define MROWS (TT*BB)          // 262144

// ---------------------------------------------------------------------------
// Scratch (device globals; no cudaMalloc allowed)
// g_h1 is reused as the hs buffer (h_t history) after the W2 GEMM consumed it.
// ---------------------------------------------------------------------------
__device__ float g_h1[(size_t)MROWS * 128];   // encoder layer-1 out / hs
__device__ float g_h2[(size_t)MROWS * 32];    // encoder layer-2 out
__device__ float g_h3[(size_t)MROWS * 128];   // encoder layer-3 out
__device__ float g_Z [(size_t)MROWS * 512];   // precomputed input gates + biases

// ---------------------------------------------------------------------------
// f32x2 packed-FMA helpers (exact fp32 math; 2 MACs per issued inst)
// ---------------------------------------------------------------------------
__device__ __forceinline__ void ffma2(uint64_t& acc, uint64_t a, uint64_t b) {
    asm("fma.rn.f32x2 %0, %1, %2, %0;" : "+l"(acc) : "l"(a), "l"(b));
}
__device__ __forceinline__ uint64_t pack2(float x, float y) {
    uint64_t r;
    asm("mov.b64 %0, {%1, %2};" : "=l"(r) : "f"(x), "f"(y));
    return r;
}
__device__ __forceinline__ void unpack2(uint64_t v, float& lo, float& hi) {
    asm("mov.b64 {%0, %1}, %2;" : "=f"(lo), "=f"(hi) : "l"(v));
}

// ---------------------------------------------------------------------------
// Fast nonlinearities (MUFU; fma pipe stays free)
// ---------------------------------------------------------------------------
__device__ __forceinline__ float sigm_fast(float x) {
    x = fminf(fmaxf(x, -30.f), 30.f);
    return __fdividef(1.f, 1.f + __expf(-x));
}
__device__ __forceinline__ float tanh_fast(float x) {
    x = fminf(fmaxf(x, -15.f), 15.f);
    float e = __expf(-2.f * x);
    return __fdividef(1.f - e, 1.f + e);
}

// ---------------------------------------------------------------------------
// 2-CTA/SM full-intensity GEMM (R16, unchanged).
// ---------------------------------------------------------------------------
template<int KT, int NT, bool RELU>
__global__ void __launch_bounds__(256, 2) gemm_b3(
    const float* __restrict__ A, const float* __restrict__ W,
    const float* __restrict__ bias1, const float* __restrict__ bias2,
    float* __restrict__ C, int N)
{
    constexpr int BP  = NT + 4;
    constexpr int CPT = NT / 32;
    constexpr int NG  = CPT / 4;

    extern __shared__ float smg[];
    float* As = smg;                // 64 k x 64 rows
    float* Bs = smg + 64 * 64;      // 64 k x BP

    const int  tid   = threadIdx.x;
    const int  lane  = tid & 31;
    const int  wid   = tid >> 5;
    const int  rbase = wid * 8;
    const int  cg    = lane * 4;
    const long row0  = (long)blockIdx.x * 64;
    const int  c0    = blockIdx.y * NT;

    uint64_t acc2[4][CPT];
    #pragma unroll
    for (int rp = 0; rp < 4; ++rp)
        #pragma unroll
        for (int c = 0; c < CPT; ++c) acc2[rp][c] = 0ull;

    for (int kc = 0; kc < KT; kc += 64) {
        for (int idx = tid; idx < 16 * 64; idx += 256) {
            int kq = idx >> 6, r = idx & 63;
            float4 v = *reinterpret_cast<const float4*>(
                A + (row0 + r) * KT + kc + kq * 4);
            As[(kq*4+0)*64 + r] = v.x;
            As[(kq*4+1)*64 + r] = v.y;
            As[(kq*4+2)*64 + r] = v.z;
            As[(kq*4+3)*64 + r] = v.w;
        }
        for (int idx = tid; idx < 16 * NT; idx += 256) {
            int kq = idx / NT, jj = idx % NT;
            float4 v = *reinterpret_cast<const float4*>(
                W + (long)(c0 + jj) * KT + kc + kq * 4);
            Bs[(kq*4+0)*BP + jj] = v.x;
            Bs[(kq*4+1)*BP + jj] = v.y;
            Bs[(kq*4+2)*BP + jj] = v.z;
            Bs[(kq*4+3)*BP + jj] = v.w;
        }
        __syncthreads();

        #pragma unroll 4
        for (int k = 0; k < 64; ++k) {
            ulonglong2 av0 = *reinterpret_cast<const ulonglong2*>(&As[k * 64 + rbase]);
            ulonglong2 av1 = *reinterpret_cast<const ulonglong2*>(&As[k * 64 + rbase + 4]);
            uint64_t ap[4] = {av0.x, av0.y, av1.x, av1.y};
            float bb[CPT];
            #pragma unroll
            for (int g = 0; g < NG; ++g) {
                float4 bv = *reinterpret_cast<const float4*>(&Bs[k * BP + g * 128 + cg]);
                bb[g*4+0] = bv.x; bb[g*4+1] = bv.y; bb[g*4+2] = bv.z; bb[g*4+3] = bv.w;
            }
            #pragma unroll
            for (int c = 0; c < CPT; ++c) {
                uint64_t bd = pack2(bb[c], bb[c]);
                #pragma unroll
                for (int rp = 0; rp < 4; ++rp)
                    ffma2(acc2[rp][c], ap[rp], bd);
            }
        }
        __syncthreads();
    }

    float acc[8][CPT];
    #pragma unroll
    for (int rp = 0; rp < 4; ++rp)
        #pragma unroll
        for (int c = 0; c < CPT; ++c)
            unpack2(acc2[rp][c], acc[2*rp][c], acc[2*rp+1][c]);

    float bsum[CPT];
    #pragma unroll
    for (int g = 0; g < NG; ++g)
        #pragma unroll
        for (int c = 0; c < 4; ++c) {
            int col = c0 + g * 128 + cg + c;
            bsum[g*4+c] = bias1[col] + (bias2 ? bias2[col] : 0.f);
        }
    #pragma unroll
    for (int i = 0; i < 8; ++i) {
        long row = row0 + rbase + i;
        #pragma unroll
        for (int g = 0; g < NG; ++g) {
            float4 o;
            o.x = acc[i][g*4+0] + bsum[g*4+0];
            o.y = acc[i][g*4+1] + bsum[g*4+1];
            o.z = acc[i][g*4+2] + bsum[g*4+2];
            o.w = acc[i][g*4+3] + bsum[g*4+3];
            if (RELU) {
                o.x = fmaxf(o.x, 0.f); o.y = fmaxf(o.y, 0.f);
                o.z = fmaxf(o.z, 0.f); o.w = fmaxf(o.w, 0.f);
            }
            *reinterpret_cast<float4*>(C + row * N + c0 + g * 128 + cg) = o;
        }
    }
}

// ---------------------------------------------------------------------------
// OLD proven GEMM (kept for the small layers W2 / W3)
// ---------------------------------------------------------------------------
template<int KT, int NT, bool RELU>
__global__ void __launch_bounds__(256, 2) gemm_kernel(
    const float* __restrict__ A, const float* __restrict__ W,
    const float* __restrict__ bias1, const float* __restrict__ bias2,
    float* __restrict__ C, int N)
{
    constexpr int AP  = 68;
    constexpr int BP  = NT + 4;
    constexpr int KQ  = KT / 4;
    constexpr int CPT = NT / 32;

    extern __shared__ float smg[];
    float* As = smg;
    float* Bs = smg + KT * AP;

    const int  tid  = threadIdx.x;
    const long row0 = (long)blockIdx.x * 64;
    const int  c0   = blockIdx.y * NT;

    for (int idx = tid; idx < KQ * 64; idx += 256) {
        int kq = idx / 64, r = idx % 64;
        float4 v = *reinterpret_cast<const float4*>(A + (row0 + r) * KT + kq * 4);
        As[(kq*4+0)*AP + r] = v.x;
        As[(kq*4+1)*AP + r] = v.y;
        As[(kq*4+2)*AP + r] = v.z;
        As[(kq*4+3)*AP + r] = v.w;
    }
    for (int idx = tid; idx < KQ * NT; idx += 256) {
        int kq = idx / NT, jj = idx % NT;
        float4 v = *reinterpret_cast<const float4*>(W + (long)(c0 + jj) * KT + kq * 4);
        Bs[(kq*4+0)*BP + jj] = v.x;
        Bs[(kq*4+1)*BP + jj] = v.y;
        Bs[(kq*4+2)*BP + jj] = v.z;
        Bs[(kq*4+3)*BP + jj] = v.w;
    }
    __syncthreads();

    const int tx = tid & 31, ty = tid >> 5;
    uint64_t acc2[4][CPT];
    #pragma unroll
    for (int i2 = 0; i2 < 4; ++i2)
        #pragma unroll
        for (int c = 0; c < CPT; ++c) acc2[i2][c] = 0ull;

    #pragma unroll 8
    for (int k = 0; k < KT; ++k) {
        ulonglong2 av0 = *reinterpret_cast<const ulonglong2*>(&As[k * AP + ty * 8]);
        ulonglong2 av1 = *reinterpret_cast<const ulonglong2*>(&As[k * AP + ty * 8 + 4]);
        uint64_t ap[4] = {av0.x, av0.y, av1.x, av1.y};
        float bb[CPT];
        if constexpr (CPT == 4) {
            float4 bv = *reinterpret_cast<const float4*>(&Bs[k * BP + tx * 4]);
            bb[0] = bv.x; bb[1] = bv.y; bb[2] = bv.z; bb[3] = bv.w;
        } else {
            bb[0] = Bs[k * BP + tx];
        }
        #pragma unroll
        for (int c = 0; c < CPT; ++c) {
            uint64_t bd = pack2(bb[c], bb[c]);
            #pragma unroll
            for (int i2 = 0; i2 < 4; ++i2)
                ffma2(acc2[i2][c], ap[i2], bd);
        }
    }

    float acc[8][CPT];
    #pragma unroll
    for (int i2 = 0; i2 < 4; ++i2)
        #pragma unroll
        for (int c = 0; c < CPT; ++c)
            unpack2(acc2[i2][c], acc[2*i2][c], acc[2*i2+1][c]);

    if constexpr (CPT == 4) {
        float bsum[4];
        #pragma unroll
        for (int c = 0; c < 4; ++c) {
            int col = c0 + tx * 4 + c;
            bsum[c] = bias1[col] + (bias2 ? bias2[col] : 0.f);
        }
        #pragma unroll
        for (int i = 0; i < 8; ++i) {
            long row = row0 + ty * 8 + i;
            float4 o;
            o.x = acc[i][0] + bsum[0];
            o.y = acc[i][1] + bsum[1];
            o.z = acc[i][2] + bsum[2];
            o.w = acc[i][3] + bsum[3];
            if (RELU) {
                o.x = fmaxf(o.x, 0.f); o.y = fmaxf(o.y, 0.f);
                o.z = fmaxf(o.z, 0.f); o.w = fmaxf(o.w, 0.f);
            }
            *reinterpret_cast<float4*>(C + row * N + c0 + tx * 4) = o;
        }
    } else {
        int col = c0 + tx;
        float bsum = bias1[col] + (bias2 ? bias2[col] : 0.f);
        #pragma unroll
        for (int i = 0; i < 8; ++i) {
            long row = row0 + ty * 8 + i;
            float v = acc[i][0] + bsum;
            if (RELU) v = fmaxf(v, 0.f);
            C[row * N + col] = v;
        }
    }
}

// ---------------------------------------------------------------------------
// LSTM recurrence (heads removed; hs stored to global).
// 128 CTAs x 512 threads; 8 lanes/CTA; Whh fp16 smem; f32x2 matvec.
// gbuf layout FIXED to [b][gate] -> all LDS/STS are 1-wavefront.
// ---------------------------------------------------------------------------
#define OFF_WSH   0                         // 512*128 half   = 131072
#define OFF_CBUF  131072                    // 8*128 f32      =   4096
#define OFF_HP    135168                    // 4*128 float2   =   4096
#define OFF_GBUF  139264                    // 8*512 f32      =  16384
#define OFF_MS    155648                    // 2*8 f32        =     64
#define SMEM_LSTM 155712

__global__ void __launch_bounds__(512, 1) lstm_kernel(
    const float* __restrict__ Z,    const float* __restrict__ done,
    const float* __restrict__ h0,   const float* __restrict__ c0,
    const float* __restrict__ Whh,  float* __restrict__ hs)
{
    extern __shared__ char smraw[];
    __half*  wsh  = reinterpret_cast<__half*>(smraw + OFF_WSH);
    float*   cbuf = reinterpret_cast<float*>(smraw + OFF_CBUF);
    float2*  hp   = reinterpret_cast<float2*>(smraw + OFF_HP);
    float*   gbuf = reinterpret_cast<float*>(smraw + OFF_GBUF);
    float*   ms   = reinterpret_cast<float*>(smraw + OFF_MS);

    const int tid = threadIdx.x;
    const int gb0 = blockIdx.x * 8;        // 128 CTAs x 8 lanes = 1024

    for (int idx = tid; idx < 512 * 128; idx += 512) {
        int jj = idx >> 7, k = idx & 127;
        wsh[((k >> 2) << 11) + (jj << 2) + (k & 3)] = __float2half(Whh[idx]);
    }
    for (int idx = tid; idx < 8 * 128; idx += 512) {
        int b = idx >> 7, u = idx & 127;
        cbuf[idx] = c0[(gb0 + b) * HH + u];
    }
    for (int idx = tid; idx < 4 * 128; idx += 512) {
        int p = idx >> 7, k = idx & 127;
        hp[p * 128 + k] = make_float2(h0[(gb0 + 2*p) * HH + k],
                                      h0[(gb0 + 2*p + 1) * HH + k]);
    }
    if (tid < 8)  ms[tid]  = 1.f - done[gb0 + tid];
    __syncthreads();

    const int j    = tid;
    const int type = j >> 7;

    for (int t = 0; t < TT; ++t) {
        const int slot  = (t & 1) * 8;
        const int nslot = ((t + 1) & 1) * 8;

        // ---- Phase A: gates = sigma( m_t * (Whh @ h) + Z ) ----
        float zr[8];
        const long zbase = ((long)t * BB + gb0) * 512 + j;
        #pragma unroll
        for (int b = 0; b < 8; ++b)
            zr[b] = Z[zbase + (long)b * 512];
        float dn = 0.f;
        if (tid < 8)
            dn = (t < TT - 1) ? done[(t + 1) * BB + gb0 + tid] : 0.f;
        float mk[8];
        #pragma unroll
        for (int b = 0; b < 8; ++b) mk[b] = ms[slot + b];

        uint64_t acc2[4] = {0ull, 0ull, 0ull, 0ull};
        #pragma unroll 4
        for (int k4 = 0; k4 < 32; ++k4) {
            uint2 wr = *reinterpret_cast<const uint2*>(wsh + (k4 << 11) + (j << 2));
            float2 w01 = __half22float2(*reinterpret_cast<const __half2*>(&wr.x));
            float2 w23 = __half22float2(*reinterpret_cast<const __half2*>(&wr.y));
            uint64_t wd0 = pack2(w01.x, w01.x);
            uint64_t wd1 = pack2(w01.y, w01.y);
            uint64_t wd2 = pack2(w23.x, w23.x);
            uint64_t wd3 = pack2(w23.y, w23.y);
            ulonglong2 ha[4], hb[4];
            #pragma unroll
            for (int p = 0; p < 4; ++p) {
                ha[p] = *reinterpret_cast<const ulonglong2*>(&hp[(p << 7) + (k4 << 2)]);
                hb[p] = *reinterpret_cast<const ulonglong2*>(&hp[(p << 7) + (k4 << 2) + 2]);
            }
            #pragma unroll
            for (int p = 0; p < 4; ++p) ffma2(acc2[p], wd0, ha[p].x);
            #pragma unroll
            for (int p = 0; p < 4; ++p) ffma2(acc2[p], wd1, ha[p].y);
            #pragma unroll
            for (int p = 0; p < 4; ++p) ffma2(acc2[p], wd2, hb[p].x);
            #pragma unroll
            for (int p = 0; p < 4; ++p) ffma2(acc2[p], wd3, hb[p].y);
        }
        float av[8];
        #pragma unroll
        for (int p = 0; p < 4; ++p) unpack2(acc2[p], av[2*p], av[2*p+1]);
        #pragma unroll
        for (int b = 0; b < 8; ++b) {
            float v = fmaf(av[b], mk[b], zr[b]);
            float gv = (type == 2) ? tanh_fast(v) : sigm_fast(v);
            gbuf[(b << 9) + j] = gv;           // [b][gate]: 1-wf stores
        }
        if (tid < 8) ms[nslot + tid] = 1.f - dn;
        __syncthreads();                       // BARRIER 1

        // ---- Phase B: c,h update; h -> hp (smem) + hs (global) ----
        #pragma unroll
        for (int it = 0; it < 2; ++it) {
            int idx = tid + it * 512;
            int b = idx >> 7, u = idx & 127;
            float m = ms[slot + b];
            int gbase = (b << 9) + u;          // [b][gate]: 1-wf loads
            float iv = gbuf[gbase];
            float fv = gbuf[gbase + 128];
            float gg = gbuf[gbase + 256];
            float ov = gbuf[gbase + 384];
            float cv = fmaf(fv, cbuf[idx] * m, iv * gg);
            float hv = ov * tanh_fast(cv);
            cbuf[idx] = cv;
            reinterpret_cast<float*>(hp)[(((b >> 1) << 7) + u) * 2 + (b & 1)] = hv;
            hs[((long)t * BB + gb0 + b) * 128 + u] = hv;   // coalesced STG
        }
        __syncthreads();                       // BARRIER 2
    }
}

// ---------------------------------------------------------------------------
// Post-pass head GEMM: out[r][0:18] = hs[r] @ Wa^T + ba ; out[r][18] = hs[r]@Wc + bc
// 2048 CTAs x 128 rows; 256 threads; thread = (row, col-half of 10).
// ---------------------------------------------------------------------------
#define S_HEAD ((128*128 + 20*132 + 32) * 4)

__global__ void __launch_bounds__(256) head_kernel(
    const float* __restrict__ hs, const float* __restrict__ Wa,
    const float* __restrict__ ba, const float* __restrict__ Wc,
    const float* __restrict__ bc, float* __restrict__ out)
{
    extern __shared__ float smh[];
    float* As = smh;                 // [k][row] 128x128
    float* Wt = smh + 128 * 128;     // [a][k]   20x132 (a=19 zero pad)
    float* bs = Wt + 20 * 132;       // 20

    const int tid = threadIdx.x;
    const long row0 = (long)blockIdx.x * 128;

    // Stage h tile transposed
    for (int idx = tid; idx < 128 * 32; idx += 256) {
        int kq = idx >> 7, r = idx & 127;
        float4 v = *reinterpret_cast<const float4*>(hs + (row0 + r) * 128 + kq * 4);
        As[(kq*4+0)*128 + r] = v.x;
        As[(kq*4+1)*128 + r] = v.y;
        As[(kq*4+2)*128 + r] = v.z;
        As[(kq*4+3)*128 + r] = v.w;
    }
    // Stage head weights (row 18 = Wc, row 19 = zeros)
    for (int idx = tid; idx < 20 * 128; idx += 256) {
        int a = idx >> 7, k = idx & 127;
        Wt[a * 132 + k] = (a < 18) ? Wa[a * 128 + k] : (a == 18 ? Wc[k] : 0.f);
    }
    if (tid < 20) bs[tid] = (tid < 18) ? ba[tid] : (tid == 18 ? bc[0] : 0.f);
    __syncthreads();

    const int rr = tid & 127;        // row within tile
    const int hi = tid >> 7;         // 0 or 1 (warp-uniform)
    const int a0 = hi * 10;          // cols a0..a0+9 (guard <19 at store)

    float acc[10];
    #pragma unroll
    for (int c = 0; c < 10; ++c) acc[c] = 0.f;

    #pragma unroll 4
    for (int k4 = 0; k4 < 32; ++k4) {
        float h0v = As[(k4*4+0)*128 + rr];
        float h1v = As[(k4*4+1)*128 + rr];
        float h2v = As[(k4*4+2)*128 + rr];
        float h3v = As[(k4*4+3)*128 + rr];
        #pragma unroll
        for (int c = 0; c < 10; ++c) {
            float4 w = *reinterpret_cast<const float4*>(&Wt[(a0 + c) * 132 + k4 * 4]);
            acc[c] = fmaf(h0v, w.x, acc[c]);
            acc[c] = fmaf(h1v, w.y, acc[c]);
            acc[c] = fmaf(h2v, w.z, acc[c]);
            acc[c] = fmaf(h3v, w.w, acc[c]);
        }
    }

    const long row = row0 + rr;
    #pragma unroll
    for (int c = 0; c < 10; ++c) {
        int col = a0 + c;
        if (col < 19)
            out[row * 19 + col] = acc[c] + bs[col];
    }
}

// ---------------------------------------------------------------------------
// Host launcher
// ---------------------------------------------------------------------------
extern "C" void kernel_launch(void* const* d_in, const int* in_sizes, int n_in,
                              void* d_out, int out_size)
{
    const float* x    = (const float*)d_in[0];
    const float* done = (const float*)d_in[1];
    const float* h0   = (const float*)d_in[2];
    const float* c0   = (const float*)d_in[3];
    const float* W1   = (const float*)d_in[4];
    const float* b1   = (const float*)d_in[5];
    const float* W2   = (const float*)d_in[6];
    const float* b2   = (const float*)d_in[7];
    const float* W3   = (const float*)d_in[8];
    const float* b3   = (const float*)d_in[9];
    const float* Wih  = (const float*)d_in[10];
    const float* Whh  = (const float*)d_in[11];
    const float* bih  = (const float*)d_in[12];
    const float* bhh  = (const float*)d_in[13];
    const float* Wa   = (const float*)d_in[14];
    const float* ba   = (const float*)d_in[15];
    const float* Wc   = (const float*)d_in[16];
    const float* bc   = (const float*)d_in[17];
    float* out = (float*)d_out;

    float *h1p, *h2p, *h3p, *Zp;
    cudaGetSymbolAddress((void**)&h1p, g_h1);
    cudaGetSymbolAddress((void**)&h2p, g_h2);
    cudaGetSymbolAddress((void**)&h3p, g_h3);
    cudaGetSymbolAddress((void**)&Zp,  g_Z);

    const int S_B3_256 = (64 * 64 + 64 * 260) * 4;   //  82944
    const int S_B3_128 = (64 * 64 + 64 * 132) * 4;   //  50176
    const int S_128_32 = (128 * 68 + 128 * 36) * 4;  //  53248
    const int S_32_128 = (32  * 68 + 32 * 132) * 4;  //  25600

    cudaFuncSetAttribute(gemm_b3<128, 128, true>,
                         cudaFuncAttributeMaxDynamicSharedMemorySize, S_B3_128);
    cudaFuncSetAttribute(gemm_b3<128, 256, false>,
                         cudaFuncAttributeMaxDynamicSharedMemorySize, S_B3_256);
    cudaFuncSetAttribute(gemm_kernel<128, 32, true>,
                         cudaFuncAttributeMaxDynamicSharedMemorySize, S_128_32);
    cudaFuncSetAttribute(gemm_kernel<32, 128, true>,
                         cudaFuncAttributeMaxDynamicSharedMemorySize, S_32_128);
    cudaFuncSetAttribute(lstm_kernel,
                         cudaFuncAttributeMaxDynamicSharedMemorySize, SMEM_LSTM);
    cudaFuncSetAttribute(head_kernel,
                         cudaFuncAttributeMaxDynamicSharedMemorySize, S_HEAD);

    const int NB64 = MROWS / 64;   // 4096 row tiles

    // Encoder
    gemm_b3<128, 128, true><<<dim3(NB64, 1), 256, S_B3_128>>>(
        x,   W1, b1, nullptr, h1p, 128);
    gemm_kernel<128, 32, true><<<dim3(NB64, 1), 256, S_128_32>>>(
        h1p, W2, b2, nullptr, h2p, 32);
    gemm_kernel<32, 128, true><<<dim3(NB64, 1), 256, S_32_128>>>(
        h2p, W3, b3, nullptr, h3p, 128);
    // Input projection: Z = hid @ Wih^T + bih + bhh
    gemm_b3<128, 256, false><<<dim3(NB64, 2), 256, S_B3_256>>>(
        h3p, Wih, bih, bhh, Zp, 512);

    // Recurrence (h history into g_h1, which is free after the W2 GEMM)
    lstm_kernel<<<128, 512, SMEM_LSTM>>>(
        Zp, done, h0, c0, Whh, h1p);

    // Heads (actor logits + critic value)
    head_kernel<<<MROWS / 128, 256, S_HEAD>>>(
        h1p, Wa, ba, Wc, bc, out);
}